// round 8
// baseline (speedup 1.0000x reference)
#include <cuda_runtime.h>
#include <cstdint>
#include <cstddef>

#define N_NODES  50000
#define N_EDGES  800000
#define N_GRAPHS 512
#define IN_DIM   128
#define HID_DIM  256
#define EMB_DIM  128
#define EPS_BN   1e-5f

#define PRE_BLOCKS 100   // all-resident persistent grid for k_pre (<=148 SMs)

// ---------------- device scratch (static; no allocation allowed) ----------------
__device__ float g_agg1[(size_t)N_NODES * IN_DIM];   // A_norm(x)            [N,128]
__device__ float g_h1r [(size_t)N_NODES * HID_DIM];  // relu(agg1@W1+b1)     [N,256]
__device__ float g_h2  [(size_t)N_NODES * EMB_DIM];  // bn1(h1r)@W2          [N,128]
__device__ int   g_rowoff[N_NODES];
__device__ int   g_csr_src[N_EDGES];
__device__ float g_dinv[N_NODES];
__device__ float g_invdeg[N_NODES];
__device__ int   g_part[PRE_BLOCKS];

// zero-memset int blob: deg | cnt | barrier counter
__device__ int   g_ibuf[2 * N_NODES + 1];
#define g_deg  (g_ibuf)
#define g_cnt  (g_ibuf + N_NODES)
#define g_barv (g_ibuf + 2 * N_NODES)

// zero-memset float blob: sum1 | sq1 | sum2 | sq2 | vmax (vmax init 0 valid: values are relu >= 0)
#define FBLOB_LEN (2 * HID_DIM + 2 * EMB_DIM + N_GRAPHS * EMB_DIM)
__device__ float g_fblob[FBLOB_LEN];
#define g_sum1 (g_fblob)
#define g_sq1  (g_fblob + HID_DIM)
#define g_sum2 (g_fblob + 2 * HID_DIM)
#define g_sq2  (g_fblob + 2 * HID_DIM + EMB_DIM)
#define g_vmax (g_fblob + 2 * HID_DIM + 2 * EMB_DIM)

// memset 0x7F -> 0x7F7F7F7F = 3.39e38 (positive; int-compare min valid for v >= 0)
__device__ float g_vmin[N_GRAPHS * EMB_DIM];

// ---------------- persistent preprocessing: deg -> scan -> fill, one kernel ----------------
__device__ __forceinline__ void grid_bar(int target) {
    __syncthreads();
    if (threadIdx.x == 0) {
        __threadfence();
        atomicAdd(g_barv, 1);
        while (atomicAdd(g_barv, 0) < target) { }
    }
    __syncthreads();
}

__global__ __launch_bounds__(256) void k_pre(const int* __restrict__ src,
                                             const int* __restrict__ dst) {
    const int b = blockIdx.x, t = threadIdx.x;
    const int gt = b * 256 + t;
    const int NT = PRE_BLOCKS * 256;

    // phase A: degree histogram
    for (int e = gt; e < N_EDGES; e += NT)
        atomicAdd(&g_deg[dst[e]], 1);
    grid_bar(PRE_BLOCKS);

    // phase B: local scan (2 items/thread, 512/block) + dinv/invdeg
    __shared__ int sh[9];
    int base = b * 512 + t * 2;
    int v0 = 0, v1 = 0;
    if (base < N_NODES) {
        v0 = g_deg[base];
        float d = (float)v0 + 1.0f;
        g_dinv[base] = rsqrtf(d);
        g_invdeg[base] = 1.0f / d;
    }
    if (base + 1 < N_NODES) {
        v1 = g_deg[base + 1];
        float d = (float)v1 + 1.0f;
        g_dinv[base + 1] = rsqrtf(d);
        g_invdeg[base + 1] = 1.0f / d;
    }
    int s = v0 + v1;
    int x = s;
    #pragma unroll
    for (int off = 1; off < 32; off <<= 1) {
        int y = __shfl_up_sync(0xffffffffu, x, off);
        if ((t & 31) >= off) x += y;
    }
    if ((t & 31) == 31) sh[t >> 5] = x;
    __syncthreads();
    if (t == 0) {
        int run = 0;
        #pragma unroll
        for (int i = 0; i < 8; i++) { int tmp = sh[i]; sh[i] = run; run += tmp; }
        g_part[b] = run;
    }
    __syncthreads();
    int texcl = sh[t >> 5] + x - s;    // exclusive prefix within block
    grid_bar(2 * PRE_BLOCKS);

    // phase C: block offset = sum of part[0..b-1]; write rowoff
    __shared__ int soff_s;
    if (t == 0) soff_s = 0;
    __syncthreads();
    int val = (t < b) ? g_part[t] : 0;     // t < b <= 99 < PRE_BLOCKS
    #pragma unroll
    for (int off = 16; off > 0; off >>= 1)
        val += __shfl_down_sync(0xffffffffu, val, off);
    if ((t & 31) == 0) atomicAdd(&soff_s, val);
    __syncthreads();
    int boff = soff_s;
    if (base < N_NODES)     g_rowoff[base]     = texcl + boff;
    if (base + 1 < N_NODES) g_rowoff[base + 1] = texcl + v0 + boff;
    grid_bar(3 * PRE_BLOCKS);

    // phase D: CSR fill
    for (int e = gt; e < N_EDGES; e += NT) {
        int d = dst[e], sn = src[e];
        int pos = g_rowoff[d] + atomicAdd(&g_cnt[d], 1);
        g_csr_src[pos] = sn;
    }
}

// ---------------- gather aggregation: warp per node (D = 128) ----------------
// FUSE2: v = relu(acc + b2); accumulate stats2; per-graph max/min (batch sorted);
//        agg2 never materialized.
template <bool FUSE2>
__global__ void k_gather(const float* __restrict__ feat, float* __restrict__ agg,
                         const float* __restrict__ bias, const int* __restrict__ batch) {
    __shared__ float ssum[FUSE2 ? 128 : 1];
    __shared__ float ssq [FUSE2 ? 128 : 1];
    __shared__ float sv  [FUSE2 ? 8 * 128 : 1];
    __shared__ int   sb  [FUSE2 ? 8 : 1];
    int tid = threadIdx.x;
    if (FUSE2) {
        if (tid < 128) { ssum[tid] = 0.f; ssq[tid] = 0.f; }
    }
    int w = (blockIdx.x * blockDim.x + tid) >> 5;
    int lane = tid & 31;
    int wrp = tid >> 5;
    const float4* feat4 = (const float4*)feat;

    float4 acc = feat4[(size_t)w * 32 + lane];
    float selfw = g_invdeg[w];
    float dinvw = g_dinv[w];
    acc.x *= selfw; acc.y *= selfw; acc.z *= selfw; acc.w *= selfw;

    int start = g_rowoff[w];
    int end   = start + g_deg[w];
    for (int base = start; base < end; base += 32) {
        int e = base + lane;
        int   s_l = 0;
        float c_l = 0.f;
        if (e < end) {
            s_l = g_csr_src[e];
            c_l = g_dinv[s_l] * dinvw;
        }
        int cnt = min(32, end - base);
        for (int j = 0; j < cnt; j++) {
            int   s = __shfl_sync(0xffffffffu, s_l, j);
            float c = __shfl_sync(0xffffffffu, c_l, j);
            float4 v = feat4[(size_t)s * 32 + lane];
            acc.x = fmaf(v.x, c, acc.x);
            acc.y = fmaf(v.y, c, acc.y);
            acc.z = fmaf(v.z, c, acc.z);
            acc.w = fmaf(v.w, c, acc.w);
        }
    }
    if (!FUSE2) {
        ((float4*)agg)[(size_t)w * 32 + lane] = acc;
    } else {
        float4 b = ((const float4*)bias)[lane];
        acc.x = fmaxf(acc.x + b.x, 0.f);
        acc.y = fmaxf(acc.y + b.y, 0.f);
        acc.z = fmaxf(acc.z + b.z, 0.f);
        acc.w = fmaxf(acc.w + b.w, 0.f);
        atomicAdd(&ssum[lane * 4 + 0], acc.x);
        atomicAdd(&ssum[lane * 4 + 1], acc.y);
        atomicAdd(&ssum[lane * 4 + 2], acc.z);
        atomicAdd(&ssum[lane * 4 + 3], acc.w);
        atomicAdd(&ssq[lane * 4 + 0], acc.x * acc.x);
        atomicAdd(&ssq[lane * 4 + 1], acc.y * acc.y);
        atomicAdd(&ssq[lane * 4 + 2], acc.z * acc.z);
        atomicAdd(&ssq[lane * 4 + 3], acc.w * acc.w);
        *(float4*)&sv[wrp * 128 + lane * 4] = acc;
        if (lane == 0) sb[wrp] = batch[w];
        __syncthreads();
        if (tid < 128) {
            atomicAdd(&g_sum2[tid], ssum[tid]);
            atomicAdd(&g_sq2[tid], ssq[tid]);
            float rmax = __int_as_float(0xFF800000);
            float rmin = __int_as_float(0x7F800000);
            int cur = sb[0];
            #pragma unroll
            for (int ww = 0; ww < 8; ww++) {
                int bid = sb[ww];
                if (bid != cur) {
                    atomicMax((int*)&g_vmax[cur * 128 + tid], __float_as_int(rmax));
                    atomicMin((int*)&g_vmin[cur * 128 + tid], __float_as_int(rmin));
                    rmax = __int_as_float(0xFF800000);
                    rmin = __int_as_float(0x7F800000);
                    cur = bid;
                }
                float vv = sv[ww * 128 + tid];
                rmax = fmaxf(rmax, vv);
                rmin = fminf(rmin, vv);
            }
            atomicMax((int*)&g_vmax[cur * 128 + tid], __float_as_int(rmax));
            atomicMin((int*)&g_vmin[cur * 128 + tid], __float_as_int(rmin));
        }
    }
}

// ================= tf32 mma.sync GEMM =================
__device__ __forceinline__ uint32_t f2tf32(float f) {
    uint32_t r; asm("cvt.rna.tf32.f32 %0, %1;" : "=r"(r) : "f"(f)); return r;
}
__device__ __forceinline__ void mma8(float& c0, float& c1, float& c2, float& c3,
                                     uint32_t a0, uint32_t a1, uint32_t a2, uint32_t a3,
                                     uint32_t b0, uint32_t b1) {
    asm volatile(
        "mma.sync.aligned.m16n8k8.row.col.f32.tf32.tf32.f32 "
        "{%0,%1,%2,%3}, {%4,%5,%6,%7}, {%8,%9}, {%0,%1,%2,%3};"
        : "+f"(c0), "+f"(c1), "+f"(c2), "+f"(c3)
        : "r"(a0), "r"(a1), "r"(a2), "r"(a3), "r"(b0), "r"(b1));
}

// C[M,NC] = (NORM? bn1(A) : A)[M,KD] @ W[KD,NC] (+bias,relu)
// CTA tile 128x128; 8 warps 4(M)x2(N); warp tile 32x64; tf32 HMMA.
template <int KD, int NC, bool RELU, bool NORM, bool STATS>
__global__ __launch_bounds__(256) void k_mma(const float* __restrict__ A,
                                             const float* __restrict__ W,
                                             const float* __restrict__ bias,
                                             const float* __restrict__ gamma,
                                             const float* __restrict__ beta,
                                             float* __restrict__ C, int M) {
    constexpr int STR = 136;
    constexpr int NCHUNK = KD / 32;
    extern __shared__ uint32_t smem_u[];
    uint32_t* Bs = smem_u;               // KD * STR
    uint32_t* As = smem_u + KD * STR;    // 2 * 32 * STR
    float* sc1 = (float*)(smem_u + KD * STR + 2 * 32 * STR);       // [KD] when NORM
    float* sh1 = sc1 + (NORM ? KD : 0);

    const int tid  = threadIdx.x;
    const int wid  = tid >> 5;
    const int lane = tid & 31;
    const int g = lane >> 2, t = lane & 3;
    const int wm = wid & 3, wn = wid >> 2;
    const int bm = blockIdx.x * 128;
    const int bn = blockIdx.y * 128;

    if (NORM) {
        const float invM = 1.0f / (float)N_NODES;
        for (int i = tid; i < KD; i += 256) {
            float m = g_sum1[i] * invM;
            float var = g_sq1[i] * invM - m * m;
            float sc = gamma[i] * rsqrtf(var + EPS_BN);
            sc1[i] = sc;
            sh1[i] = beta[i] - m * sc;
        }
    }

    // ---- load B tile (cols [bn,bn+128)) as tf32 ----
    for (int i = tid; i < KD * 32; i += 256) {
        int k = i >> 5;
        int n = (i & 31) * 4;
        float4 w = *(const float4*)(W + (size_t)k * NC + bn + n);
        uint4 u;
        u.x = f2tf32(w.x); u.y = f2tf32(w.y); u.z = f2tf32(w.z); u.w = f2tf32(w.w);
        *(uint4*)&Bs[k * STR + n] = u;
    }
    if (NORM) __syncthreads();   // sc1/sh1 ready before loadA uses them

    const int la_row = tid >> 1;
    const int la_k   = (tid & 1) * 16;
    const int gr_a   = bm + la_row;

    float acc[2][8][4];
    #pragma unroll
    for (int f = 0; f < 2; f++)
        #pragma unroll
        for (int j = 0; j < 8; j++)
            #pragma unroll
            for (int q = 0; q < 4; q++) acc[f][j][q] = 0.f;

    auto loadA = [&](int c, float4* pre) {
        int k0 = c * 32 + la_k;
        #pragma unroll
        for (int i = 0; i < 4; i++) {
            float4 v = make_float4(0.f, 0.f, 0.f, 0.f);
            if (gr_a < M) v = *(const float4*)(A + (size_t)gr_a * KD + k0 + i * 4);
            if (NORM) {
                int kk = k0 + i * 4;
                v.x = fmaf(v.x, sc1[kk + 0], sh1[kk + 0]);
                v.y = fmaf(v.y, sc1[kk + 1], sh1[kk + 1]);
                v.z = fmaf(v.z, sc1[kk + 2], sh1[kk + 2]);
                v.w = fmaf(v.w, sc1[kk + 3], sh1[kk + 3]);
            }
            pre[i] = v;
        }
    };
    auto storeA = [&](int buf, const float4* pre) {
        uint32_t* Ab = As + buf * (32 * STR);
        #pragma unroll
        for (int i = 0; i < 4; i++) {
            int kl = la_k + i * 4;
            Ab[(kl + 0) * STR + la_row] = f2tf32(pre[i].x);
            Ab[(kl + 1) * STR + la_row] = f2tf32(pre[i].y);
            Ab[(kl + 2) * STR + la_row] = f2tf32(pre[i].z);
            Ab[(kl + 3) * STR + la_row] = f2tf32(pre[i].w);
        }
    };
    auto compute = [&](int buf, int c) {
        const uint32_t* Ab = As + buf * (32 * STR);
        #pragma unroll
        for (int ks = 0; ks < 4; ks++) {
            int kt = ks * 8 + t;
            uint32_t a[2][4];
            #pragma unroll
            for (int f = 0; f < 2; f++) {
                int row = wm * 32 + f * 16 + g;
                a[f][0] = Ab[kt * STR + row];
                a[f][1] = Ab[kt * STR + row + 8];
                a[f][2] = Ab[(kt + 4) * STR + row];
                a[f][3] = Ab[(kt + 4) * STR + row + 8];
            }
            int kabs = c * 32 + ks * 8 + t;
            #pragma unroll
            for (int j = 0; j < 8; j++) {
                int col = wn * 64 + j * 8 + g;
                uint32_t b0 = Bs[kabs * STR + col];
                uint32_t b1 = Bs[(kabs + 4) * STR + col];
                mma8(acc[0][j][0], acc[0][j][1], acc[0][j][2], acc[0][j][3],
                     a[0][0], a[0][1], a[0][2], a[0][3], b0, b1);
                mma8(acc[1][j][0], acc[1][j][1], acc[1][j][2], acc[1][j][3],
                     a[1][0], a[1][1], a[1][2], a[1][3], b0, b1);
            }
        }
    };

    float4 pre[4];
    loadA(0, pre);
    storeA(0, pre);
    __syncthreads();
    int buf = 0;
    for (int c = 1; c < NCHUNK; c++) {
        loadA(c, pre);
        compute(buf, c - 1);
        storeA(buf ^ 1, pre);
        __syncthreads();
        buf ^= 1;
    }
    compute(buf, NCHUNK - 1);

    // ---- epilogue: regs -> gmem (+bias,relu) ; fused stats ----
    #pragma unroll
    for (int f = 0; f < 2; f++) {
        int r0 = bm + wm * 32 + f * 16 + g;
        #pragma unroll
        for (int j = 0; j < 8; j++) {
            int gc = bn + wn * 64 + j * 8 + 2 * t;
            float2 v0 = make_float2(acc[f][j][0], acc[f][j][1]);
            float2 v1 = make_float2(acc[f][j][2], acc[f][j][3]);
            if (RELU) {
                float b0v = bias[gc], b1v = bias[gc + 1];
                v0.x = fmaxf(v0.x + b0v, 0.f); v0.y = fmaxf(v0.y + b1v, 0.f);
                v1.x = fmaxf(v1.x + b0v, 0.f); v1.y = fmaxf(v1.y + b1v, 0.f);
            }
            if (r0 < M)     *(float2*)(C + (size_t)r0 * NC + gc)       = v0;
            if (r0 + 8 < M) *(float2*)(C + (size_t)(r0 + 8) * NC + gc) = v1;
            if (STATS) {
                bool m0 = r0 < M, m1 = (r0 + 8) < M;
                float s0 = (m0 ? v0.x : 0.f) + (m1 ? v1.x : 0.f);
                float s1 = (m0 ? v0.y : 0.f) + (m1 ? v1.y : 0.f);
                float q0 = (m0 ? v0.x * v0.x : 0.f) + (m1 ? v1.x * v1.x : 0.f);
                float q1 = (m0 ? v0.y * v0.y : 0.f) + (m1 ? v1.y * v1.y : 0.f);
                #pragma unroll
                for (int off = 4; off < 32; off <<= 1) {
                    s0 += __shfl_xor_sync(0xffffffffu, s0, off);
                    s1 += __shfl_xor_sync(0xffffffffu, s1, off);
                    q0 += __shfl_xor_sync(0xffffffffu, q0, off);
                    q1 += __shfl_xor_sync(0xffffffffu, q1, off);
                }
                if (lane < 4) {
                    int cc = bn + wn * 64 + j * 8 + 2 * lane;
                    atomicAdd(&g_sum1[cc], s0);
                    atomicAdd(&g_sum1[cc + 1], s1);
                    atomicAdd(&g_sq1[cc], q0);
                    atomicAdd(&g_sq1[cc + 1], q1);
                }
            }
        }
    }
}

// ---------------- final: apply BN2 affine to per-graph max/min ----------------
__global__ void k_final(const float* __restrict__ gamma, const float* __restrict__ beta,
                        float* __restrict__ out) {
    __shared__ float sc[EMB_DIM], shf[EMB_DIM];
    int tid = threadIdx.x;
    if (tid < EMB_DIM) {
        const float invM = 1.0f / (float)N_NODES;
        float m = g_sum2[tid] * invM;
        float var = g_sq2[tid] * invM - m * m;
        float s = gamma[tid] * rsqrtf(var + EPS_BN);
        sc[tid] = s;
        shf[tid] = beta[tid] - m * s;
    }
    __syncthreads();
    int idx = blockIdx.x * blockDim.x + tid;
    if (idx >= N_GRAPHS * EMB_DIM) return;
    int c = idx & 127;
    float s = sc[c];
    float v = (s >= 0.f) ? g_vmax[idx] : g_vmin[idx];
    out[idx] = fmaf(s, v, shf[c]);
}

// ---------------- launch ----------------
extern "C" void kernel_launch(void* const* d_in, const int* in_sizes, int n_in,
                              void* d_out, int out_size) {
    const float* x      = (const float*)d_in[0];
    const int*   ei     = (const int*)d_in[1];
    const int*   batch  = (const int*)d_in[2];
    const float* W1     = (const float*)d_in[3];
    const float* b1     = (const float*)d_in[4];
    const float* gamma1 = (const float*)d_in[5];
    const float* beta1  = (const float*)d_in[6];
    const float* W2     = (const float*)d_in[7];
    const float* b2     = (const float*)d_in[8];
    const float* gamma2 = (const float*)d_in[9];
    const float* beta2  = (const float*)d_in[10];
    float* out = (float*)d_out;

    const int* src = ei;
    const int* dst = ei + N_EDGES;

    float *p_agg1, *p_h1r, *p_h2, *p_fblob, *p_vmin;
    int *p_ibuf;
    cudaGetSymbolAddress((void**)&p_agg1,  g_agg1);
    cudaGetSymbolAddress((void**)&p_h1r,   g_h1r);
    cudaGetSymbolAddress((void**)&p_h2,    g_h2);
    cudaGetSymbolAddress((void**)&p_ibuf,  g_ibuf);
    cudaGetSymbolAddress((void**)&p_fblob, g_fblob);
    cudaGetSymbolAddress((void**)&p_vmin,  g_vmin);

    const int SMEM1 = (IN_DIM * 136 + 2 * 32 * 136) * 4;                // 104448
    const int SMEM2 = (HID_DIM * 136 + 2 * 32 * 136 + 2 * HID_DIM) * 4; // 176128
    cudaFuncSetAttribute(k_mma<IN_DIM, HID_DIM, true, false, true>,
                         cudaFuncAttributeMaxDynamicSharedMemorySize, SMEM1);
    cudaFuncSetAttribute(k_mma<HID_DIM, EMB_DIM, false, true, false>,
                         cudaFuncAttributeMaxDynamicSharedMemorySize, SMEM2);
    const int MTILES = (N_NODES + 127) / 128;                           // 391

    // init via memsets (vmax=0 valid since values >= 0; vmin=0x7F7F7F7F=3.39e38)
    cudaMemsetAsync(p_ibuf, 0, (2 * N_NODES + 1) * sizeof(int));
    cudaMemsetAsync(p_fblob, 0, FBLOB_LEN * sizeof(float));
    cudaMemsetAsync(p_vmin, 0x7F, N_GRAPHS * EMB_DIM * sizeof(float));

    // preprocessing: deg + scan + fill in one persistent kernel
    k_pre<<<PRE_BLOCKS, 256>>>(src, dst);

    // layer 1: aggregate (linearity), then tf32 GEMM (+bias+relu+stats1)
    k_gather<false><<<(N_NODES * 32 + 255) / 256, 256>>>(x, p_agg1, nullptr, nullptr);
    {
        dim3 grid(MTILES, HID_DIM / 128);
        k_mma<IN_DIM, HID_DIM, true, false, true><<<grid, 256, SMEM1>>>(
            p_agg1, W1, b1, nullptr, nullptr, p_h1r, N_NODES);
    }

    // layer 2: GEMM (bn1 in-kernel from stats), then fused aggregate+stats2+segmax
    {
        dim3 grid(MTILES, EMB_DIM / 128);
        k_mma<HID_DIM, EMB_DIM, false, true, false><<<grid, 256, SMEM2>>>(
            p_h1r, W2, nullptr, gamma1, beta1, p_h2, N_NODES);
    }
    k_gather<true><<<(N_NODES * 32 + 255) / 256, 256>>>(p_h2, nullptr, b2, batch);

    // output: BN2 affine on per-graph extrema
    k_final<<<(N_GRAPHS * EMB_DIM + 255) / 256, 256>>>(gamma2, beta2, out);
}

// round 10
// speedup vs baseline: 1.4313x; 1.4313x over previous
#include <cuda_runtime.h>
#include <cstdint>
#include <cstddef>

#define N_NODES  50000
#define N_EDGES  800000
#define N_GRAPHS 512
#define IN_DIM   128
#define HID_DIM  256
#define EMB_DIM  128
#define EPS_BN   1e-5f

#define SCAN_TPB 256
#define SCAN_EPB 1024
#define SCAN_NBLK ((N_NODES + SCAN_EPB - 1) / SCAN_EPB)   // 49

// ---------------- device scratch (static; no allocation allowed) ----------------
__device__ float g_agg1[(size_t)N_NODES * IN_DIM];   // A_norm(x)            [N,128]
__device__ float g_h1r [(size_t)N_NODES * HID_DIM];  // relu(agg1@W1+b1)     [N,256]
__device__ float g_h2  [(size_t)N_NODES * EMB_DIM];  // bn1(h1r)@W2          [N,128]
__device__ int   g_deg [N_NODES];
__device__ int   g_rowoff[N_NODES];
__device__ int   g_cnt [N_NODES];
__device__ int   g_part[64];
__device__ int   g_csr_src[N_EDGES];
__device__ float g_coef  [N_EDGES];
__device__ float g_dinv[N_NODES];
__device__ float g_invdeg[N_NODES];
__device__ float g_sum1[HID_DIM], g_sq1[HID_DIM];
__device__ float g_sum2[EMB_DIM], g_sq2[EMB_DIM];
__device__ float g_vmax[N_GRAPHS * EMB_DIM];         // per-graph max of relu(agg2+b2)
__device__ float g_vmin[N_GRAPHS * EMB_DIM];         // per-graph min of relu(agg2+b2)

// ---------------- setup kernels ----------------
__global__ void k_zero() {
    int i = blockIdx.x * blockDim.x + threadIdx.x;
    if (i < N_NODES) { g_deg[i] = 0; g_cnt[i] = 0; }
    if (i < HID_DIM) { g_sum1[i] = 0.f; g_sq1[i] = 0.f; }
    if (i < EMB_DIM) { g_sum2[i] = 0.f; g_sq2[i] = 0.f; }
    if (i < N_GRAPHS * EMB_DIM) {
        g_vmax[i] = __int_as_float(0xFF800000);   // -inf
        g_vmin[i] = __int_as_float(0x7F800000);   // +inf
    }
}

__global__ void k_deg(const int* __restrict__ dst) {
    int e = blockIdx.x * blockDim.x + threadIdx.x;
    if (e < N_EDGES) atomicAdd(&g_deg[dst[e]], 1);
}

// exclusive scan of g_deg -> g_rowoff (3-phase); also computes dinv/invdeg
__global__ void k_scan1() {
    __shared__ int sh[SCAN_TPB / 32];
    int b = blockIdx.x, t = threadIdx.x;
    int base = b * SCAN_EPB + t * 4;
    int v[4]; int s = 0;
    #pragma unroll
    for (int q = 0; q < 4; q++) {
        int i = base + q;
        v[q] = (i < N_NODES) ? g_deg[i] : 0;
        s += v[q];
        if (i < N_NODES) {
            float d = (float)v[q] + 1.0f;
            g_dinv[i]   = rsqrtf(d);
            g_invdeg[i] = 1.0f / d;
        }
    }
    int x = s;
    #pragma unroll
    for (int off = 1; off < 32; off <<= 1) {
        int y = __shfl_up_sync(0xffffffffu, x, off);
        if ((t & 31) >= off) x += y;
    }
    if ((t & 31) == 31) sh[t >> 5] = x;
    __syncthreads();
    if (t < 32) {
        int y = (t < SCAN_TPB / 32) ? sh[t] : 0;
        #pragma unroll
        for (int off = 1; off < SCAN_TPB / 32; off <<= 1) {
            int z = __shfl_up_sync(0xffffffffu, y, off);
            if (t >= off) y += z;
        }
        if (t < SCAN_TPB / 32) sh[t] = y;
    }
    __syncthreads();
    int warpoff = (t >= 32) ? sh[(t >> 5) - 1] : 0;
    int run = warpoff + x - s;
    #pragma unroll
    for (int q = 0; q < 4; q++) { int i = base + q; if (i < N_NODES) g_rowoff[i] = run; run += v[q]; }
    if (t == SCAN_TPB - 1) g_part[b] = warpoff + x;
}

__global__ void k_scan2() {
    __shared__ int sh[64];
    int t = threadIdx.x;
    int v = (t < SCAN_NBLK) ? g_part[t] : 0;
    sh[t] = v; __syncthreads();
    for (int off = 1; off < 64; off <<= 1) {
        int y = (t >= off) ? sh[t - off] : 0;
        __syncthreads();
        sh[t] += y;
        __syncthreads();
    }
    g_part[t] = sh[t] - v;
}

__global__ void k_scan3() {
    int i = blockIdx.x * blockDim.x + threadIdx.x;
    if (i < N_NODES) g_rowoff[i] += g_part[i / SCAN_EPB];
}

__global__ void k_fill(const int* __restrict__ src, const int* __restrict__ dst) {
    int e = blockIdx.x * blockDim.x + threadIdx.x;
    if (e >= N_EDGES) return;
    int d = dst[e], s = src[e];
    int pos = g_rowoff[d] + atomicAdd(&g_cnt[d], 1);
    g_csr_src[pos] = s;
    g_coef[pos] = g_dinv[s] * g_dinv[d];
}

// ---------------- gather aggregation: warp per node (D = 128) ----------------
// FUSE2: v = relu(acc + b2); accumulate stats2; per-graph max/min (batch sorted);
//        agg2 never materialized.
template <bool FUSE2>
__global__ void k_gather(const float* __restrict__ feat, float* __restrict__ agg,
                         const float* __restrict__ bias, const int* __restrict__ batch) {
    __shared__ float ssum[FUSE2 ? 128 : 1];
    __shared__ float ssq [FUSE2 ? 128 : 1];
    __shared__ float sv  [FUSE2 ? 8 * 128 : 1];
    __shared__ int   sb  [FUSE2 ? 8 : 1];
    int tid = threadIdx.x;
    if (FUSE2) {
        if (tid < 128) { ssum[tid] = 0.f; ssq[tid] = 0.f; }
    }
    int w = (blockIdx.x * blockDim.x + tid) >> 5;
    int lane = tid & 31;
    int wrp = tid >> 5;
    const float4* feat4 = (const float4*)feat;

    float4 acc = feat4[(size_t)w * 32 + lane];
    float selfw = g_invdeg[w];
    acc.x *= selfw; acc.y *= selfw; acc.z *= selfw; acc.w *= selfw;

    int start = g_rowoff[w];
    int end   = start + g_deg[w];
    for (int base = start; base < end; base += 32) {
        int e = base + lane;
        int   s_l = 0;
        float c_l = 0.f;
        if (e < end) { s_l = g_csr_src[e]; c_l = g_coef[e]; }
        int cnt = min(32, end - base);
        for (int j = 0; j < cnt; j++) {
            int   s = __shfl_sync(0xffffffffu, s_l, j);
            float c = __shfl_sync(0xffffffffu, c_l, j);
            float4 v = feat4[(size_t)s * 32 + lane];
            acc.x = fmaf(v.x, c, acc.x);
            acc.y = fmaf(v.y, c, acc.y);
            acc.z = fmaf(v.z, c, acc.z);
            acc.w = fmaf(v.w, c, acc.w);
        }
    }
    if (!FUSE2) {
        ((float4*)agg)[(size_t)w * 32 + lane] = acc;
    } else {
        float4 b = ((const float4*)bias)[lane];
        acc.x = fmaxf(acc.x + b.x, 0.f);
        acc.y = fmaxf(acc.y + b.y, 0.f);
        acc.z = fmaxf(acc.z + b.z, 0.f);
        acc.w = fmaxf(acc.w + b.w, 0.f);
        atomicAdd(&ssum[lane * 4 + 0], acc.x);
        atomicAdd(&ssum[lane * 4 + 1], acc.y);
        atomicAdd(&ssum[lane * 4 + 2], acc.z);
        atomicAdd(&ssum[lane * 4 + 3], acc.w);
        atomicAdd(&ssq[lane * 4 + 0], acc.x * acc.x);
        atomicAdd(&ssq[lane * 4 + 1], acc.y * acc.y);
        atomicAdd(&ssq[lane * 4 + 2], acc.z * acc.z);
        atomicAdd(&ssq[lane * 4 + 3], acc.w * acc.w);
        *(float4*)&sv[wrp * 128 + lane * 4] = acc;
        if (lane == 0) sb[wrp] = batch[w];
        __syncthreads();
        if (tid < 128) {
            atomicAdd(&g_sum2[tid], ssum[tid]);
            atomicAdd(&g_sq2[tid], ssq[tid]);
            float rmax = __int_as_float(0xFF800000);
            float rmin = __int_as_float(0x7F800000);
            int cur = sb[0];
            #pragma unroll
            for (int ww = 0; ww < 8; ww++) {
                int bid = sb[ww];
                if (bid != cur) {
                    atomicMax((int*)&g_vmax[cur * 128 + tid], __float_as_int(rmax));
                    atomicMin((int*)&g_vmin[cur * 128 + tid], __float_as_int(rmin));
                    rmax = __int_as_float(0xFF800000);
                    rmin = __int_as_float(0x7F800000);
                    cur = bid;
                }
                float vv = sv[ww * 128 + tid];
                rmax = fmaxf(rmax, vv);
                rmin = fminf(rmin, vv);
            }
            atomicMax((int*)&g_vmax[cur * 128 + tid], __float_as_int(rmax));
            atomicMin((int*)&g_vmin[cur * 128 + tid], __float_as_int(rmin));
        }
    }
}

// ================= tf32 mma.sync GEMM — BOTH operands K-chunk streamed =================
__device__ __forceinline__ uint32_t f2tf32(float f) {
    uint32_t r; asm("cvt.rna.tf32.f32 %0, %1;" : "=r"(r) : "f"(f)); return r;
}
__device__ __forceinline__ void mma8(float& c0, float& c1, float& c2, float& c3,
                                     uint32_t a0, uint32_t a1, uint32_t a2, uint32_t a3,
                                     uint32_t b0, uint32_t b1) {
    asm volatile(
        "mma.sync.aligned.m16n8k8.row.col.f32.tf32.tf32.f32 "
        "{%0,%1,%2,%3}, {%4,%5,%6,%7}, {%8,%9}, {%0,%1,%2,%3};"
        : "+f"(c0), "+f"(c1), "+f"(c2), "+f"(c3)
        : "r"(a0), "r"(a1), "r"(a2), "r"(a3), "r"(b0), "r"(b1));
}

// C[M,NC] = (NORM? bn1(A) : A)[M,KD] @ W[KD,NC] (+bias,relu)
// CTA tile 128x128; 8 warps 4(M)x2(N); warp tile 32x64; tf32 HMMA.
// A and B both staged in 32-wide K chunks, double-buffered -> ~70KB smem -> 2 CTAs/SM.
template <int KD, int NC, bool RELU, bool NORM, bool STATS>
__global__ __launch_bounds__(256, 2) void k_mma(const float* __restrict__ A,
                                                const float* __restrict__ W,
                                                const float* __restrict__ bias,
                                                const float* __restrict__ gamma,
                                                const float* __restrict__ beta,
                                                float* __restrict__ C, int M) {
    constexpr int STR = 136;             // 136 % 32 == 8 -> conflict-free frag loads
    constexpr int NCHUNK = KD / 32;
    extern __shared__ uint32_t smem_u[];
    uint32_t* As = smem_u;                    // 2 * 32 * STR
    uint32_t* Bs = smem_u + 2 * 32 * STR;     // 2 * 32 * STR
    float* sc1 = (float*)(smem_u + 4 * 32 * STR);   // [KD] when NORM
    float* sh1 = sc1 + (NORM ? KD : 0);

    const int tid  = threadIdx.x;
    const int lane = tid & 31;
    const int wid  = tid >> 5;
    const int g = lane >> 2, t = lane & 3;
    const int wm = wid & 3, wn = wid >> 2;
    const int bm = blockIdx.x * 128;
    const int bn = blockIdx.y * 128;

    if (NORM) {
        const float invM = 1.0f / (float)N_NODES;
        for (int i = tid; i < KD; i += 256) {
            float m = g_sum1[i] * invM;
            float var = g_sq1[i] * invM - m * m;
            float sc = gamma[i] * rsqrtf(var + EPS_BN);
            sc1[i] = sc;
            sh1[i] = beta[i] - m * sc;
        }
        __syncthreads();
    }

    const int la_row = tid >> 1;
    const int la_k   = (tid & 1) * 16;
    const int gr_a   = bm + la_row;

    float acc[2][8][4];
    #pragma unroll
    for (int f = 0; f < 2; f++)
        #pragma unroll
        for (int j = 0; j < 8; j++)
            #pragma unroll
            for (int q = 0; q < 4; q++) acc[f][j][q] = 0.f;

    auto loadA = [&](int c, float4* pre) {
        int k0 = c * 32 + la_k;
        #pragma unroll
        for (int i = 0; i < 4; i++) {
            float4 v = make_float4(0.f, 0.f, 0.f, 0.f);
            if (gr_a < M) v = *(const float4*)(A + (size_t)gr_a * KD + k0 + i * 4);
            if (NORM) {
                int kk = k0 + i * 4;
                v.x = fmaf(v.x, sc1[kk + 0], sh1[kk + 0]);
                v.y = fmaf(v.y, sc1[kk + 1], sh1[kk + 1]);
                v.z = fmaf(v.z, sc1[kk + 2], sh1[kk + 2]);
                v.w = fmaf(v.w, sc1[kk + 3], sh1[kk + 3]);
            }
            pre[i] = v;
        }
    };
    auto storeA = [&](int buf, const float4* pre) {
        uint32_t* Ab = As + buf * (32 * STR);
        #pragma unroll
        for (int i = 0; i < 4; i++) {
            int kl = la_k + i * 4;
            Ab[(kl + 0) * STR + la_row] = f2tf32(pre[i].x);
            Ab[(kl + 1) * STR + la_row] = f2tf32(pre[i].y);
            Ab[(kl + 2) * STR + la_row] = f2tf32(pre[i].z);
            Ab[(kl + 3) * STR + la_row] = f2tf32(pre[i].w);
        }
    };
    auto loadB = [&](int c, float4* pre) {
        #pragma unroll
        for (int q = 0; q < 4; q++) {
            int i = tid + q * 256;           // 0..1023
            int kl = i >> 5;                 // 0..31
            int n  = (i & 31) * 4;           // 0..124
            pre[q] = *(const float4*)(W + (size_t)(c * 32 + kl) * NC + bn + n);
        }
    };
    auto storeB = [&](int buf, const float4* pre) {
        uint32_t* Bb = Bs + buf * (32 * STR);
        #pragma unroll
        for (int q = 0; q < 4; q++) {
            int i = tid + q * 256;
            int kl = i >> 5;
            int n  = (i & 31) * 4;
            uint4 u;
            u.x = f2tf32(pre[q].x); u.y = f2tf32(pre[q].y);
            u.z = f2tf32(pre[q].z); u.w = f2tf32(pre[q].w);
            *(uint4*)&Bb[kl * STR + n] = u;
        }
    };
    auto compute = [&](int buf) {
        const uint32_t* Ab = As + buf * (32 * STR);
        const uint32_t* Bb = Bs + buf * (32 * STR);
        #pragma unroll
        for (int ks = 0; ks < 4; ks++) {
            int kt = ks * 8 + t;
            uint32_t a[2][4];
            #pragma unroll
            for (int f = 0; f < 2; f++) {
                int row = wm * 32 + f * 16 + g;
                a[f][0] = Ab[kt * STR + row];
                a[f][1] = Ab[kt * STR + row + 8];
                a[f][2] = Ab[(kt + 4) * STR + row];
                a[f][3] = Ab[(kt + 4) * STR + row + 8];
            }
            #pragma unroll
            for (int j = 0; j < 8; j++) {
                int col = wn * 64 + j * 8 + g;
                uint32_t b0 = Bb[kt * STR + col];
                uint32_t b1 = Bb[(kt + 4) * STR + col];
                mma8(acc[0][j][0], acc[0][j][1], acc[0][j][2], acc[0][j][3],
                     a[0][0], a[0][1], a[0][2], a[0][3], b0, b1);
                mma8(acc[1][j][0], acc[1][j][1], acc[1][j][2], acc[1][j][3],
                     a[1][0], a[1][1], a[1][2], a[1][3], b0, b1);
            }
        }
    };

    float4 preA[4], preB[4];
    loadA(0, preA); loadB(0, preB);
    storeA(0, preA); storeB(0, preB);
    __syncthreads();
    int buf = 0;
    for (int c = 1; c < NCHUNK; c++) {
        loadA(c, preA); loadB(c, preB);
        compute(buf);
        storeA(buf ^ 1, preA); storeB(buf ^ 1, preB);
        __syncthreads();
        buf ^= 1;
    }
    compute(buf);

    // ---- epilogue: regs -> gmem (+bias,relu) ; fused stats ----
    #pragma unroll
    for (int f = 0; f < 2; f++) {
        int r0 = bm + wm * 32 + f * 16 + g;
        #pragma unroll
        for (int j = 0; j < 8; j++) {
            int gc = bn + wn * 64 + j * 8 + 2 * t;
            float2 v0 = make_float2(acc[f][j][0], acc[f][j][1]);
            float2 v1 = make_float2(acc[f][j][2], acc[f][j][3]);
            if (RELU) {
                float b0v = bias[gc], b1v = bias[gc + 1];
                v0.x = fmaxf(v0.x + b0v, 0.f); v0.y = fmaxf(v0.y + b1v, 0.f);
                v1.x = fmaxf(v1.x + b0v, 0.f); v1.y = fmaxf(v1.y + b1v, 0.f);
            }
            if (r0 < M)     *(float2*)(C + (size_t)r0 * NC + gc)       = v0;
            if (r0 + 8 < M) *(float2*)(C + (size_t)(r0 + 8) * NC + gc) = v1;
            if (STATS) {
                bool m0 = r0 < M, m1 = (r0 + 8) < M;
                float s0 = (m0 ? v0.x : 0.f) + (m1 ? v1.x : 0.f);
                float s1 = (m0 ? v0.y : 0.f) + (m1 ? v1.y : 0.f);
                float q0 = (m0 ? v0.x * v0.x : 0.f) + (m1 ? v1.x * v1.x : 0.f);
                float q1 = (m0 ? v0.y * v0.y : 0.f) + (m1 ? v1.y * v1.y : 0.f);
                #pragma unroll
                for (int off = 4; off < 32; off <<= 1) {
                    s0 += __shfl_xor_sync(0xffffffffu, s0, off);
                    s1 += __shfl_xor_sync(0xffffffffu, s1, off);
                    q0 += __shfl_xor_sync(0xffffffffu, q0, off);
                    q1 += __shfl_xor_sync(0xffffffffu, q1, off);
                }
                if (lane < 4) {
                    int cc = bn + wn * 64 + j * 8 + 2 * lane;
                    atomicAdd(&g_sum1[cc], s0);
                    atomicAdd(&g_sum1[cc + 1], s1);
                    atomicAdd(&g_sq1[cc], q0);
                    atomicAdd(&g_sq1[cc + 1], q1);
                }
            }
        }
    }
}

// ---------------- final: apply BN2 affine to per-graph max/min ----------------
__global__ void k_final(const float* __restrict__ gamma, const float* __restrict__ beta,
                        float* __restrict__ out) {
    __shared__ float sc[EMB_DIM], shf[EMB_DIM];
    int tid = threadIdx.x;
    if (tid < EMB_DIM) {
        const float invM = 1.0f / (float)N_NODES;
        float m = g_sum2[tid] * invM;
        float var = g_sq2[tid] * invM - m * m;
        float s = gamma[tid] * rsqrtf(var + EPS_BN);
        sc[tid] = s;
        shf[tid] = beta[tid] - m * s;
    }
    __syncthreads();
    int idx = blockIdx.x * blockDim.x + tid;
    if (idx >= N_GRAPHS * EMB_DIM) return;
    int c = idx & 127;
    float s = sc[c];
    float v = (s >= 0.f) ? g_vmax[idx] : g_vmin[idx];
    out[idx] = fmaf(s, v, shf[c]);
}

// ---------------- launch ----------------
extern "C" void kernel_launch(void* const* d_in, const int* in_sizes, int n_in,
                              void* d_out, int out_size) {
    const float* x      = (const float*)d_in[0];
    const int*   ei     = (const int*)d_in[1];
    const int*   batch  = (const int*)d_in[2];
    const float* W1     = (const float*)d_in[3];
    const float* b1     = (const float*)d_in[4];
    const float* gamma1 = (const float*)d_in[5];
    const float* beta1  = (const float*)d_in[6];
    const float* W2     = (const float*)d_in[7];
    const float* b2     = (const float*)d_in[8];
    const float* gamma2 = (const float*)d_in[9];
    const float* beta2  = (const float*)d_in[10];
    float* out = (float*)d_out;

    const int* src = ei;
    const int* dst = ei + N_EDGES;

    float *p_agg1, *p_h1r, *p_h2;
    cudaGetSymbolAddress((void**)&p_agg1, g_agg1);
    cudaGetSymbolAddress((void**)&p_h1r,  g_h1r);
    cudaGetSymbolAddress((void**)&p_h2,   g_h2);

    const int SMEM1 = (4 * 32 * 136) * 4;                    // 69632
    const int SMEM2 = (4 * 32 * 136 + 2 * HID_DIM) * 4;      // 71680
    cudaFuncSetAttribute(k_mma<IN_DIM, HID_DIM, true, false, true>,
                         cudaFuncAttributeMaxDynamicSharedMemorySize, SMEM1);
    cudaFuncSetAttribute(k_mma<HID_DIM, EMB_DIM, false, true, false>,
                         cudaFuncAttributeMaxDynamicSharedMemorySize, SMEM2);
    const int MTILES = (N_NODES + 127) / 128;                // 391

    // init + degrees + CSR build
    k_zero<<<(N_GRAPHS * EMB_DIM + 255) / 256, 256>>>();
    k_deg<<<(N_EDGES + 255) / 256, 256>>>(dst);
    k_scan1<<<SCAN_NBLK, SCAN_TPB>>>();
    k_scan2<<<1, 64>>>();
    k_scan3<<<(N_NODES + 255) / 256, 256>>>();
    k_fill<<<(N_EDGES + 255) / 256, 256>>>(src, dst);

    // layer 1: aggregate (linearity), then tf32 GEMM (+bias+relu+stats1)
    k_gather<false><<<(N_NODES * 32 + 255) / 256, 256>>>(x, p_agg1, nullptr, nullptr);
    {
        dim3 grid(MTILES, HID_DIM / 128);
        k_mma<IN_DIM, HID_DIM, true, false, true><<<grid, 256, SMEM1>>>(
            p_agg1, W1, b1, nullptr, nullptr, p_h1r, N_NODES);
    }

    // layer 2: GEMM (bn1 in-kernel from stats), then fused aggregate+stats2+segmax
    {
        dim3 grid(MTILES, EMB_DIM / 128);
        k_mma<HID_DIM, EMB_DIM, false, true, false><<<grid, 256, SMEM2>>>(
            p_h1r, W2, nullptr, gamma1, beta1, p_h2, N_NODES);
    }
    k_gather<true><<<(N_NODES * 32 + 255) / 256, 256>>>(p_h2, nullptr, b2, batch);

    // output: BN2 affine on per-graph extrema
    k_final<<<(N_GRAPHS * EMB_DIM + 255) / 256, 256>>>(gamma2, beta2, out);
}

// round 12
// speedup vs baseline: 1.4536x; 1.0156x over previous
#include <cuda_runtime.h>
#include <cstdint>
#include <cstddef>

#define N_NODES  50000
#define N_EDGES  800000
#define N_GRAPHS 512
#define IN_DIM   128
#define HID_DIM  256
#define EMB_DIM  128
#define EPS_BN   1e-5f

#define SCAN_TPB 256
#define SCAN_EPB 1024
#define SCAN_NBLK ((N_NODES + SCAN_EPB - 1) / SCAN_EPB)   // 49

// ---------------- device scratch (static; no allocation allowed) ----------------
__device__ float g_agg1[(size_t)N_NODES * IN_DIM];   // A_norm(x)            [N,128]
__device__ float g_h1r [(size_t)N_NODES * HID_DIM];  // relu(agg1@W1+b1)     [N,256]
__device__ float g_h2  [(size_t)N_NODES * EMB_DIM];  // bn1(h1r)@W2          [N,128]
__device__ int   g_deg [N_NODES];
__device__ int   g_rowoff[N_NODES];
__device__ int   g_cnt [N_NODES];
__device__ int   g_part[64];                          // block aggregates, init -1
__device__ int   g_csr_src[N_EDGES];
__device__ float g_coef  [N_EDGES];
__device__ float g_dinv[N_NODES];
__device__ float g_invdeg[N_NODES];
__device__ float g_sum1[HID_DIM], g_sq1[HID_DIM];
__device__ float g_sum2[EMB_DIM], g_sq2[EMB_DIM];
__device__ float g_vmax[N_GRAPHS * EMB_DIM];         // per-graph max of relu(agg2+b2)
__device__ float g_vmin[N_GRAPHS * EMB_DIM];         // per-graph min of relu(agg2+b2)

// ---------------- setup kernels ----------------
__global__ void k_zero() {
    int i = blockIdx.x * blockDim.x + threadIdx.x;
    if (i < N_NODES) { g_deg[i] = 0; g_cnt[i] = 0; }
    if (i < HID_DIM) { g_sum1[i] = 0.f; g_sq1[i] = 0.f; }
    if (i < EMB_DIM) { g_sum2[i] = 0.f; g_sq2[i] = 0.f; }
    if (i < 64) g_part[i] = -1;
    if (i < N_GRAPHS * EMB_DIM) {
        g_vmax[i] = __int_as_float(0xFF800000);   // -inf
        g_vmin[i] = __int_as_float(0x7F800000);   // +inf
    }
}

__global__ void k_deg(const int* __restrict__ dst) {
    int e = blockIdx.x * blockDim.x + threadIdx.x;
    if (e < N_EDGES) atomicAdd(&g_deg[dst[e]], 1);
}

// single-kernel exclusive scan of g_deg -> g_rowoff with decoupled lookback
// (49 blocks, all resident simultaneously); also computes dinv/invdeg.
__global__ __launch_bounds__(SCAN_TPB) void k_scan() {
    __shared__ int sh[SCAN_TPB / 32];
    __shared__ int boff_s;
    int b = blockIdx.x, t = threadIdx.x;
    int base = b * SCAN_EPB + t * 4;
    int v[4]; int s = 0;
    #pragma unroll
    for (int q = 0; q < 4; q++) {
        int i = base + q;
        v[q] = (i < N_NODES) ? g_deg[i] : 0;
        s += v[q];
        if (i < N_NODES) {
            float d = (float)v[q] + 1.0f;
            g_dinv[i]   = rsqrtf(d);
            g_invdeg[i] = 1.0f / d;
        }
    }
    int x = s;
    #pragma unroll
    for (int off = 1; off < 32; off <<= 1) {
        int y = __shfl_up_sync(0xffffffffu, x, off);
        if ((t & 31) >= off) x += y;
    }
    if ((t & 31) == 31) sh[t >> 5] = x;
    if (t == 0) boff_s = 0;
    __syncthreads();
    if (t < 32) {
        int y = (t < SCAN_TPB / 32) ? sh[t] : 0;
        #pragma unroll
        for (int off = 1; off < SCAN_TPB / 32; off <<= 1) {
            int z = __shfl_up_sync(0xffffffffu, y, off);
            if (t >= off) y += z;
        }
        if (t < SCAN_TPB / 32) sh[t] = y;
    }
    __syncthreads();
    int warpoff = (t >= 32) ? sh[(t >> 5) - 1] : 0;
    int local_excl = warpoff + x - s;         // exclusive prefix within block
    int block_total = sh[SCAN_TPB / 32 - 1];  // block aggregate

    // publish aggregate (>= 0; slots were initialized to -1)
    if (t == 0) atomicExch(&g_part[b], block_total);
    // lookback: sum all predecessor aggregates (they publish ~simultaneously)
    for (int i = t; i < b; i += SCAN_TPB) {
        int pv;
        do { pv = atomicAdd(&g_part[i], 0); } while (pv < 0);
        atomicAdd(&boff_s, pv);
    }
    __syncthreads();
    int run = local_excl + boff_s;
    #pragma unroll
    for (int q = 0; q < 4; q++) {
        int i = base + q;
        if (i < N_NODES) g_rowoff[i] = run;
        run += v[q];
    }
}

__global__ void k_fill(const int* __restrict__ src, const int* __restrict__ dst) {
    int e = blockIdx.x * blockDim.x + threadIdx.x;
    if (e >= N_EDGES) return;
    int d = dst[e], s = src[e];
    int pos = g_rowoff[d] + atomicAdd(&g_cnt[d], 1);
    g_csr_src[pos] = s;
    g_coef[pos] = g_dinv[s] * g_dinv[d];
}

// ---------------- gather aggregation: warp per node (D = 128) ----------------
// FUSE2: v = relu(acc + b2); accumulate stats2; per-graph max/min (batch sorted);
//        agg2 never materialized.
template <bool FUSE2>
__global__ void k_gather(const float* __restrict__ feat, float* __restrict__ agg,
                         const float* __restrict__ bias, const int* __restrict__ batch) {
    __shared__ float ssum[FUSE2 ? 128 : 1];
    __shared__ float ssq [FUSE2 ? 128 : 1];
    __shared__ float sv  [FUSE2 ? 8 * 128 : 1];
    __shared__ int   sb  [FUSE2 ? 8 : 1];
    int tid = threadIdx.x;
    if (FUSE2) {
        if (tid < 128) { ssum[tid] = 0.f; ssq[tid] = 0.f; }
    }
    int w = (blockIdx.x * blockDim.x + tid) >> 5;
    int lane = tid & 31;
    int wrp = tid >> 5;
    const float4* feat4 = (const float4*)feat;

    float4 acc = feat4[(size_t)w * 32 + lane];
    float selfw = g_invdeg[w];
    acc.x *= selfw; acc.y *= selfw; acc.z *= selfw; acc.w *= selfw;

    int start = g_rowoff[w];
    int end   = start + g_deg[w];
    for (int base = start; base < end; base += 32) {
        int e = base + lane;
        int   s_l = 0;
        float c_l = 0.f;
        if (e < end) { s_l = g_csr_src[e]; c_l = g_coef[e]; }
        int cnt = min(32, end - base);
        for (int j = 0; j < cnt; j++) {
            int   s = __shfl_sync(0xffffffffu, s_l, j);
            float c = __shfl_sync(0xffffffffu, c_l, j);
            float4 v = feat4[(size_t)s * 32 + lane];
            acc.x = fmaf(v.x, c, acc.x);
            acc.y = fmaf(v.y, c, acc.y);
            acc.z = fmaf(v.z, c, acc.z);
            acc.w = fmaf(v.w, c, acc.w);
        }
    }
    if (!FUSE2) {
        ((float4*)agg)[(size_t)w * 32 + lane] = acc;
    } else {
        float4 b = ((const float4*)bias)[lane];
        acc.x = fmaxf(acc.x + b.x, 0.f);
        acc.y = fmaxf(acc.y + b.y, 0.f);
        acc.z = fmaxf(acc.z + b.z, 0.f);
        acc.w = fmaxf(acc.w + b.w, 0.f);
        atomicAdd(&ssum[lane * 4 + 0], acc.x);
        atomicAdd(&ssum[lane * 4 + 1], acc.y);
        atomicAdd(&ssum[lane * 4 + 2], acc.z);
        atomicAdd(&ssum[lane * 4 + 3], acc.w);
        atomicAdd(&ssq[lane * 4 + 0], acc.x * acc.x);
        atomicAdd(&ssq[lane * 4 + 1], acc.y * acc.y);
        atomicAdd(&ssq[lane * 4 + 2], acc.z * acc.z);
        atomicAdd(&ssq[lane * 4 + 3], acc.w * acc.w);
        *(float4*)&sv[wrp * 128 + lane * 4] = acc;
        if (lane == 0) sb[wrp] = batch[w];
        __syncthreads();
        if (tid < 128) {
            atomicAdd(&g_sum2[tid], ssum[tid]);
            atomicAdd(&g_sq2[tid], ssq[tid]);
            float rmax = __int_as_float(0xFF800000);
            float rmin = __int_as_float(0x7F800000);
            int cur = sb[0];
            #pragma unroll
            for (int ww = 0; ww < 8; ww++) {
                int bid = sb[ww];
                if (bid != cur) {
                    atomicMax((int*)&g_vmax[cur * 128 + tid], __float_as_int(rmax));
                    atomicMin((int*)&g_vmin[cur * 128 + tid], __float_as_int(rmin));
                    rmax = __int_as_float(0xFF800000);
                    rmin = __int_as_float(0x7F800000);
                    cur = bid;
                }
                float vv = sv[ww * 128 + tid];
                rmax = fmaxf(rmax, vv);
                rmin = fminf(rmin, vv);
            }
            atomicMax((int*)&g_vmax[cur * 128 + tid], __float_as_int(rmax));
            atomicMin((int*)&g_vmin[cur * 128 + tid], __float_as_int(rmin));
        }
    }
}

// ================= tf32 mma.sync GEMM — K-chunk streamed, M-tile templated =================
__device__ __forceinline__ uint32_t f2tf32(float f) {
    uint32_t r; asm("cvt.rna.tf32.f32 %0, %1;" : "=r"(r) : "f"(f)); return r;
}
__device__ __forceinline__ void mma8(float& c0, float& c1, float& c2, float& c3,
                                     uint32_t a0, uint32_t a1, uint32_t a2, uint32_t a3,
                                     uint32_t b0, uint32_t b1) {
    asm volatile(
        "mma.sync.aligned.m16n8k8.row.col.f32.tf32.tf32.f32 "
        "{%0,%1,%2,%3}, {%4,%5,%6,%7}, {%8,%9}, {%0,%1,%2,%3};"
        : "+f"(c0), "+f"(c1), "+f"(c2), "+f"(c3)
        : "r"(a0), "r"(a1), "r"(a2), "r"(a3), "r"(b0), "r"(b1));
}

// C[M,NC] = (NORM? bn1(A) : A)[M,KD] @ W[KD,NC] (+bias,relu)
// CTA tile MT x 128 (MT = 64 or 128); 8 warps (MT/32)x(8/(MT/32)); tf32 HMMA.
// A and B staged in 32-wide K chunks, double-buffered.
template <int MT, int KD, int NC, bool RELU, bool NORM, bool STATS>
__global__ __launch_bounds__(256, 2) void k_mma(const float* __restrict__ A,
                                                const float* __restrict__ W,
                                                const float* __restrict__ bias,
                                                const float* __restrict__ gamma,
                                                const float* __restrict__ beta,
                                                float* __restrict__ C, int M) {
    constexpr int STR = 136;             // 136 % 32 == 8 -> conflict-free frag loads
    constexpr int NCHUNK = KD / 32;
    constexpr int WM = MT / 32;          // warps along M: 4 or 2
    constexpr int WN = 8 / WM;           // warps along N: 2 or 4
    constexpr int CW = 128 / WN;         // cols per warp: 64 or 32
    constexpr int JMAX = CW / 8;         // 8 or 4
    constexpr int TPR = 256 / MT;        // threads per A-row: 2 or 4
    constexpr int KPT = 32 / TPR;        // k floats per thread: 16 or 8
    constexpr int NF4 = KPT / 4;         // float4s per thread: 4 or 2

    extern __shared__ uint32_t smem_u[];
    uint32_t* As = smem_u;                    // 2 * 32 * STR
    uint32_t* Bs = smem_u + 2 * 32 * STR;     // 2 * 32 * STR
    float* sc1 = (float*)(smem_u + 4 * 32 * STR);   // [KD] when NORM
    float* sh1 = sc1 + (NORM ? KD : 0);

    const int tid  = threadIdx.x;
    const int lane = tid & 31;
    const int wid  = tid >> 5;
    const int g = lane >> 2, t = lane & 3;
    const int wm = wid % WM, wn = wid / WM;
    const int bm = blockIdx.x * MT;
    const int bn = blockIdx.y * 128;

    if (NORM) {
        const float invM = 1.0f / (float)N_NODES;
        for (int i = tid; i < KD; i += 256) {
            float m = g_sum1[i] * invM;
            float var = g_sq1[i] * invM - m * m;
            float sc = gamma[i] * rsqrtf(var + EPS_BN);
            sc1[i] = sc;
            sh1[i] = beta[i] - m * sc;
        }
        __syncthreads();
    }

    const int la_row = tid / TPR;
    const int la_k   = (tid % TPR) * KPT;
    const int gr_a   = bm + la_row;

    float acc[2][JMAX][4];
    #pragma unroll
    for (int f = 0; f < 2; f++)
        #pragma unroll
        for (int j = 0; j < JMAX; j++)
            #pragma unroll
            for (int q = 0; q < 4; q++) acc[f][j][q] = 0.f;

    auto loadA = [&](int c, float4* pre) {
        int k0 = c * 32 + la_k;
        #pragma unroll
        for (int i = 0; i < NF4; i++) {
            float4 v = make_float4(0.f, 0.f, 0.f, 0.f);
            if (gr_a < M) v = *(const float4*)(A + (size_t)gr_a * KD + k0 + i * 4);
            if (NORM) {
                int kk = k0 + i * 4;
                v.x = fmaf(v.x, sc1[kk + 0], sh1[kk + 0]);
                v.y = fmaf(v.y, sc1[kk + 1], sh1[kk + 1]);
                v.z = fmaf(v.z, sc1[kk + 2], sh1[kk + 2]);
                v.w = fmaf(v.w, sc1[kk + 3], sh1[kk + 3]);
            }
            pre[i] = v;
        }
    };
    auto storeA = [&](int buf, const float4* pre) {
        uint32_t* Ab = As + buf * (32 * STR);
        #pragma unroll
        for (int i = 0; i < NF4; i++) {
            int kl = la_k + i * 4;
            Ab[(kl + 0) * STR + la_row] = f2tf32(pre[i].x);
            Ab[(kl + 1) * STR + la_row] = f2tf32(pre[i].y);
            Ab[(kl + 2) * STR + la_row] = f2tf32(pre[i].z);
            Ab[(kl + 3) * STR + la_row] = f2tf32(pre[i].w);
        }
    };
    auto loadB = [&](int c, float4* pre) {
        #pragma unroll
        for (int q = 0; q < 4; q++) {
            int i = tid + q * 256;           // 0..1023
            int kl = i >> 5;                 // 0..31
            int n  = (i & 31) * 4;           // 0..124
            pre[q] = *(const float4*)(W + (size_t)(c * 32 + kl) * NC + bn + n);
        }
    };
    auto storeB = [&](int buf, const float4* pre) {
        uint32_t* Bb = Bs + buf * (32 * STR);
        #pragma unroll
        for (int q = 0; q < 4; q++) {
            int i = tid + q * 256;
            int kl = i >> 5;
            int n  = (i & 31) * 4;
            uint4 u;
            u.x = f2tf32(pre[q].x); u.y = f2tf32(pre[q].y);
            u.z = f2tf32(pre[q].z); u.w = f2tf32(pre[q].w);
            *(uint4*)&Bb[kl * STR + n] = u;
        }
    };
    auto compute = [&](int buf) {
        const uint32_t* Ab = As + buf * (32 * STR);
        const uint32_t* Bb = Bs + buf * (32 * STR);
        #pragma unroll
        for (int ks = 0; ks < 4; ks++) {
            int kt = ks * 8 + t;
            uint32_t a[2][4];
            #pragma unroll
            for (int f = 0; f < 2; f++) {
                int row = wm * 32 + f * 16 + g;
                a[f][0] = Ab[kt * STR + row];
                a[f][1] = Ab[kt * STR + row + 8];
                a[f][2] = Ab[(kt + 4) * STR + row];
                a[f][3] = Ab[(kt + 4) * STR + row + 8];
            }
            #pragma unroll
            for (int j = 0; j < JMAX; j++) {
                int col = wn * CW + j * 8 + g;
                uint32_t b0 = Bb[kt * STR + col];
                uint32_t b1 = Bb[(kt + 4) * STR + col];
                mma8(acc[0][j][0], acc[0][j][1], acc[0][j][2], acc[0][j][3],
                     a[0][0], a[0][1], a[0][2], a[0][3], b0, b1);
                mma8(acc[1][j][0], acc[1][j][1], acc[1][j][2], acc[1][j][3],
                     a[1][0], a[1][1], a[1][2], a[1][3], b0, b1);
            }
        }
    };

    float4 preA[NF4], preB[4];
    loadA(0, preA); loadB(0, preB);
    storeA(0, preA); storeB(0, preB);
    __syncthreads();
    int buf = 0;
    for (int c = 1; c < NCHUNK; c++) {
        loadA(c, preA); loadB(c, preB);
        compute(buf);
        storeA(buf ^ 1, preA); storeB(buf ^ 1, preB);
        __syncthreads();
        buf ^= 1;
    }
    compute(buf);

    // ---- epilogue: regs -> gmem (+bias,relu) ; fused stats ----
    #pragma unroll
    for (int f = 0; f < 2; f++) {
        int r0 = bm + wm * 32 + f * 16 + g;
        #pragma unroll
        for (int j = 0; j < JMAX; j++) {
            int gc = bn + wn * CW + j * 8 + 2 * t;
            float2 v0 = make_float2(acc[f][j][0], acc[f][j][1]);
            float2 v1 = make_float2(acc[f][j][2], acc[f][j][3]);
            if (RELU) {
                float b0v = bias[gc], b1v = bias[gc + 1];
                v0.x = fmaxf(v0.x + b0v, 0.f); v0.y = fmaxf(v0.y + b1v, 0.f);
                v1.x = fmaxf(v1.x + b0v, 0.f); v1.y = fmaxf(v1.y + b1v, 0.f);
            }
            if (r0 < M)     *(float2*)(C + (size_t)r0 * NC + gc)       = v0;
            if (r0 + 8 < M) *(float2*)(C + (size_t)(r0 + 8) * NC + gc) = v1;
            if (STATS) {
                bool m0 = r0 < M, m1 = (r0 + 8) < M;
                float s0 = (m0 ? v0.x : 0.f) + (m1 ? v1.x : 0.f);
                float s1 = (m0 ? v0.y : 0.f) + (m1 ? v1.y : 0.f);
                float q0 = (m0 ? v0.x * v0.x : 0.f) + (m1 ? v1.x * v1.x : 0.f);
                float q1 = (m0 ? v0.y * v0.y : 0.f) + (m1 ? v1.y * v1.y : 0.f);
                #pragma unroll
                for (int off = 4; off < 32; off <<= 1) {
                    s0 += __shfl_xor_sync(0xffffffffu, s0, off);
                    s1 += __shfl_xor_sync(0xffffffffu, s1, off);
                    q0 += __shfl_xor_sync(0xffffffffu, q0, off);
                    q1 += __shfl_xor_sync(0xffffffffu, q1, off);
                }
                if (lane < 4) {
                    int cc = bn + wn * CW + j * 8 + 2 * lane;
                    atomicAdd(&g_sum1[cc], s0);
                    atomicAdd(&g_sum1[cc + 1], s1);
                    atomicAdd(&g_sq1[cc], q0);
                    atomicAdd(&g_sq1[cc + 1], q1);
                }
            }
        }
    }
}

// ---------------- final: apply BN2 affine to per-graph max/min ----------------
__global__ void k_final(const float* __restrict__ gamma, const float* __restrict__ beta,
                        float* __restrict__ out) {
    __shared__ float sc[EMB_DIM], shf[EMB_DIM];
    int tid = threadIdx.x;
    if (tid < EMB_DIM) {
        const float invM = 1.0f / (float)N_NODES;
        float m = g_sum2[tid] * invM;
        float var = g_sq2[tid] * invM - m * m;
        float s = gamma[tid] * rsqrtf(var + EPS_BN);
        sc[tid] = s;
        shf[tid] = beta[tid] - m * s;
    }
    __syncthreads();
    int idx = blockIdx.x * blockDim.x + tid;
    if (idx >= N_GRAPHS * EMB_DIM) return;
    int c = idx & 127;
    float s = sc[c];
    float v = (s >= 0.f) ? g_vmax[idx] : g_vmin[idx];
    out[idx] = fmaf(s, v, shf[c]);
}

// ---------------- launch ----------------
extern "C" void kernel_launch(void* const* d_in, const int* in_sizes, int n_in,
                              void* d_out, int out_size) {
    const float* x      = (const float*)d_in[0];
    const int*   ei     = (const int*)d_in[1];
    const int*   batch  = (const int*)d_in[2];
    const float* W1     = (const float*)d_in[3];
    const float* b1     = (const float*)d_in[4];
    const float* gamma1 = (const float*)d_in[5];
    const float* beta1  = (const float*)d_in[6];
    const float* W2     = (const float*)d_in[7];
    const float* b2     = (const float*)d_in[8];
    const float* gamma2 = (const float*)d_in[9];
    const float* beta2  = (const float*)d_in[10];
    float* out = (float*)d_out;

    const int* src = ei;
    const int* dst = ei + N_EDGES;

    float *p_agg1, *p_h1r, *p_h2;
    cudaGetSymbolAddress((void**)&p_agg1, g_agg1);
    cudaGetSymbolAddress((void**)&p_h1r,  g_h1r);
    cudaGetSymbolAddress((void**)&p_h2,   g_h2);

    const int SMEM1 = (4 * 32 * 136) * 4;                    // 69632
    const int SMEM2 = (4 * 32 * 136 + 2 * HID_DIM) * 4;      // 71680
    cudaFuncSetAttribute(k_mma<128, IN_DIM, HID_DIM, true, false, true>,
                         cudaFuncAttributeMaxDynamicSharedMemorySize, SMEM1);
    cudaFuncSetAttribute(k_mma<64, HID_DIM, EMB_DIM, false, true, false>,
                         cudaFuncAttributeMaxDynamicSharedMemorySize, SMEM2);

    // init + degrees + CSR build (scan fused into one lookback kernel)
    k_zero<<<(N_GRAPHS * EMB_DIM + 255) / 256, 256>>>();
    k_deg<<<(N_EDGES + 255) / 256, 256>>>(dst);
    k_scan<<<SCAN_NBLK, SCAN_TPB>>>();
    k_fill<<<(N_EDGES + 255) / 256, 256>>>(src, dst);

    // layer 1: aggregate (linearity), then tf32 GEMM (+bias+relu+stats1)
    k_gather<false><<<(N_NODES * 32 + 255) / 256, 256>>>(x, p_agg1, nullptr, nullptr);
    {
        dim3 grid((N_NODES + 127) / 128, HID_DIM / 128);     // 391 x 2
        k_mma<128, IN_DIM, HID_DIM, true, false, true><<<grid, 256, SMEM1>>>(
            p_agg1, W1, b1, nullptr, nullptr, p_h1r, N_NODES);
    }

    // layer 2: GEMM with MT=64 for wave balance (782 CTAs), bn1 in-kernel
    {
        dim3 grid((N_NODES + 63) / 64, EMB_DIM / 128);       // 782 x 1
        k_mma<64, HID_DIM, EMB_DIM, false, true, false><<<grid, 256, SMEM2>>>(
            p_h1r, W2, nullptr, gamma1, beta1, p_h2, N_NODES);
    }
    k_gather<true><<<(N_NODES * 32 + 255) / 256, 256>>>(p_h2, nullptr, b2, batch);

    // output: BN2 affine on per-graph extrema
    k_final<<<(N_GRAPHS * EMB_DIM + 255) / 256, 256>>>(gamma2, beta2, out);
}

// round 13
// speedup vs baseline: 1.4647x; 1.0076x over previous
#include <cuda_runtime.h>
#include <cstdint>
#include <cstddef>

#define N_NODES  50000
#define N_EDGES  800000
#define N_GRAPHS 512
#define IN_DIM   128
#define HID_DIM  256
#define EMB_DIM  128
#define EPS_BN   1e-5f

#define SCAN_TPB 256
#define SCAN_EPB 1024
#define SCAN_NBLK ((N_NODES + SCAN_EPB - 1) / SCAN_EPB)   // 49

// ---------------- device scratch (static; no allocation allowed) ----------------
__device__ float g_agg1[(size_t)N_NODES * IN_DIM];   // A_norm(x)            [N,128]
__device__ float g_h1r [(size_t)N_NODES * HID_DIM];  // relu(agg1@W1+b1)     [N,256]
__device__ float g_h2  [(size_t)N_NODES * EMB_DIM];  // bn1(h1r)@W2          [N,128]
__device__ int   g_deg [N_NODES];
__device__ int   g_rowoff[N_NODES];
__device__ int   g_cnt [N_NODES];
__device__ int   g_part[64];                          // block aggregates, init -1
__device__ int2  g_csr [N_EDGES];                     // {src, coef as float bits}
__device__ float g_dinv[N_NODES];
__device__ float g_invdeg[N_NODES];
__device__ float g_sum1[HID_DIM], g_sq1[HID_DIM];
__device__ float g_sum2[EMB_DIM], g_sq2[EMB_DIM];
__device__ float g_vmax[N_GRAPHS * EMB_DIM];         // per-graph max of relu(agg2+b2)
__device__ float g_vmin[N_GRAPHS * EMB_DIM];         // per-graph min of relu(agg2+b2)

// ---------------- setup kernels ----------------
__global__ void k_zero() {
    int i = blockIdx.x * blockDim.x + threadIdx.x;
    if (i < N_NODES) { g_deg[i] = 0; g_cnt[i] = 0; }
    if (i < HID_DIM) { g_sum1[i] = 0.f; g_sq1[i] = 0.f; }
    if (i < EMB_DIM) { g_sum2[i] = 0.f; g_sq2[i] = 0.f; }
    if (i < 64) g_part[i] = -1;
    if (i < N_GRAPHS * EMB_DIM) {
        g_vmax[i] = __int_as_float(0xFF800000);   // -inf
        g_vmin[i] = __int_as_float(0x7F800000);   // +inf
    }
}

__global__ void k_deg(const int* __restrict__ dst) {
    int e = blockIdx.x * blockDim.x + threadIdx.x;
    if (e < N_EDGES) atomicAdd(&g_deg[dst[e]], 1);
}

// single-kernel exclusive scan of g_deg -> g_rowoff with decoupled lookback
// (49 blocks, all resident simultaneously); also computes dinv/invdeg.
__global__ __launch_bounds__(SCAN_TPB) void k_scan() {
    __shared__ int sh[SCAN_TPB / 32];
    __shared__ int boff_s;
    int b = blockIdx.x, t = threadIdx.x;
    int base = b * SCAN_EPB + t * 4;
    int v[4]; int s = 0;
    #pragma unroll
    for (int q = 0; q < 4; q++) {
        int i = base + q;
        v[q] = (i < N_NODES) ? g_deg[i] : 0;
        s += v[q];
        if (i < N_NODES) {
            float d = (float)v[q] + 1.0f;
            g_dinv[i]   = rsqrtf(d);
            g_invdeg[i] = 1.0f / d;
        }
    }
    int x = s;
    #pragma unroll
    for (int off = 1; off < 32; off <<= 1) {
        int y = __shfl_up_sync(0xffffffffu, x, off);
        if ((t & 31) >= off) x += y;
    }
    if ((t & 31) == 31) sh[t >> 5] = x;
    if (t == 0) boff_s = 0;
    __syncthreads();
    if (t < 32) {
        int y = (t < SCAN_TPB / 32) ? sh[t] : 0;
        #pragma unroll
        for (int off = 1; off < SCAN_TPB / 32; off <<= 1) {
            int z = __shfl_up_sync(0xffffffffu, y, off);
            if (t >= off) y += z;
        }
        if (t < SCAN_TPB / 32) sh[t] = y;
    }
    __syncthreads();
    int warpoff = (t >= 32) ? sh[(t >> 5) - 1] : 0;
    int local_excl = warpoff + x - s;         // exclusive prefix within block
    int block_total = sh[SCAN_TPB / 32 - 1];  // block aggregate

    if (t == 0) atomicExch(&g_part[b], block_total);
    for (int i = t; i < b; i += SCAN_TPB) {
        int pv;
        do { pv = atomicAdd(&g_part[i], 0); } while (pv < 0);
        atomicAdd(&boff_s, pv);
    }
    __syncthreads();
    int run = local_excl + boff_s;
    #pragma unroll
    for (int q = 0; q < 4; q++) {
        int i = base + q;
        if (i < N_NODES) g_rowoff[i] = run;
        run += v[q];
    }
}

__global__ void k_fill(const int* __restrict__ src, const int* __restrict__ dst) {
    int e = blockIdx.x * blockDim.x + threadIdx.x;
    if (e >= N_EDGES) return;
    int d = dst[e], s = src[e];
    int pos = g_rowoff[d] + atomicAdd(&g_cnt[d], 1);
    g_csr[pos] = make_int2(s, __float_as_int(g_dinv[s] * g_dinv[d]));
}

// ---------------- gather aggregation: warp per node (D = 128) ----------------
// FUSE2: v = relu(acc + b2); accumulate stats2; per-graph max/min (batch sorted);
//        agg2 never materialized.
template <bool FUSE2>
__global__ void k_gather(const float* __restrict__ feat, float* __restrict__ agg,
                         const float* __restrict__ bias, const int* __restrict__ batch) {
    __shared__ float ssum[FUSE2 ? 128 : 1];
    __shared__ float ssq [FUSE2 ? 128 : 1];
    __shared__ float sv  [FUSE2 ? 8 * 128 : 1];
    __shared__ int   sb  [FUSE2 ? 8 : 1];
    int tid = threadIdx.x;
    if (FUSE2) {
        if (tid < 128) { ssum[tid] = 0.f; ssq[tid] = 0.f; }
    }
    int w = (blockIdx.x * blockDim.x + tid) >> 5;
    int lane = tid & 31;
    int wrp = tid >> 5;
    const float4* feat4 = (const float4*)feat;

    float4 acc = feat4[(size_t)w * 32 + lane];
    float selfw = g_invdeg[w];
    acc.x *= selfw; acc.y *= selfw; acc.z *= selfw; acc.w *= selfw;

    int start = g_rowoff[w];
    int end   = start + g_deg[w];
    for (int base = start; base < end; base += 32) {
        int e = base + lane;
        int   s_l = 0;
        float c_l = 0.f;
        if (e < end) {
            int2 e2 = g_csr[e];
            s_l = e2.x;
            c_l = __int_as_float(e2.y);
        }
        int cnt = min(32, end - base);
        for (int j = 0; j < cnt; j++) {
            int   s = __shfl_sync(0xffffffffu, s_l, j);
            float c = __shfl_sync(0xffffffffu, c_l, j);
            float4 v = feat4[(size_t)s * 32 + lane];
            acc.x = fmaf(v.x, c, acc.x);
            acc.y = fmaf(v.y, c, acc.y);
            acc.z = fmaf(v.z, c, acc.z);
            acc.w = fmaf(v.w, c, acc.w);
        }
    }
    if (!FUSE2) {
        ((float4*)agg)[(size_t)w * 32 + lane] = acc;
    } else {
        float4 b = ((const float4*)bias)[lane];
        acc.x = fmaxf(acc.x + b.x, 0.f);
        acc.y = fmaxf(acc.y + b.y, 0.f);
        acc.z = fmaxf(acc.z + b.z, 0.f);
        acc.w = fmaxf(acc.w + b.w, 0.f);
        atomicAdd(&ssum[lane * 4 + 0], acc.x);
        atomicAdd(&ssum[lane * 4 + 1], acc.y);
        atomicAdd(&ssum[lane * 4 + 2], acc.z);
        atomicAdd(&ssum[lane * 4 + 3], acc.w);
        atomicAdd(&ssq[lane * 4 + 0], acc.x * acc.x);
        atomicAdd(&ssq[lane * 4 + 1], acc.y * acc.y);
        atomicAdd(&ssq[lane * 4 + 2], acc.z * acc.z);
        atomicAdd(&ssq[lane * 4 + 3], acc.w * acc.w);
        *(float4*)&sv[wrp * 128 + lane * 4] = acc;
        if (lane == 0) sb[wrp] = batch[w];
        __syncthreads();
        if (tid < 128) {
            atomicAdd(&g_sum2[tid], ssum[tid]);
            atomicAdd(&g_sq2[tid], ssq[tid]);
            float rmax = __int_as_float(0xFF800000);
            float rmin = __int_as_float(0x7F800000);
            int cur = sb[0];
            #pragma unroll
            for (int ww = 0; ww < 8; ww++) {
                int bid = sb[ww];
                if (bid != cur) {
                    atomicMax((int*)&g_vmax[cur * 128 + tid], __float_as_int(rmax));
                    atomicMin((int*)&g_vmin[cur * 128 + tid], __float_as_int(rmin));
                    rmax = __int_as_float(0xFF800000);
                    rmin = __int_as_float(0x7F800000);
                    cur = bid;
                }
                float vv = sv[ww * 128 + tid];
                rmax = fmaxf(rmax, vv);
                rmin = fminf(rmin, vv);
            }
            atomicMax((int*)&g_vmax[cur * 128 + tid], __float_as_int(rmax));
            atomicMin((int*)&g_vmin[cur * 128 + tid], __float_as_int(rmin));
        }
    }
}

// ================= tf32 mma.sync GEMM — K-chunk streamed, M-tile templated =================
__device__ __forceinline__ uint32_t f2tf32(float f) {
    uint32_t r; asm("cvt.rna.tf32.f32 %0, %1;" : "=r"(r) : "f"(f)); return r;
}
__device__ __forceinline__ void mma8(float& c0, float& c1, float& c2, float& c3,
                                     uint32_t a0, uint32_t a1, uint32_t a2, uint32_t a3,
                                     uint32_t b0, uint32_t b1) {
    asm volatile(
        "mma.sync.aligned.m16n8k8.row.col.f32.tf32.tf32.f32 "
        "{%0,%1,%2,%3}, {%4,%5,%6,%7}, {%8,%9}, {%0,%1,%2,%3};"
        : "+f"(c0), "+f"(c1), "+f"(c2), "+f"(c3)
        : "r"(a0), "r"(a1), "r"(a2), "r"(a3), "r"(b0), "r"(b1));
}

// C[M,NC] = (NORM? bn1(A) : A)[M,KD] @ W[KD,NC] (+bias,relu)
// CTA tile MT x 128 (MT = 64 or 128); 8 warps (MT/32)x(8/(MT/32)); tf32 HMMA.
// A and B staged in 32-wide K chunks, double-buffered.
template <int MT, int KD, int NC, bool RELU, bool NORM, bool STATS>
__global__ __launch_bounds__(256, 2) void k_mma(const float* __restrict__ A,
                                                const float* __restrict__ W,
                                                const float* __restrict__ bias,
                                                const float* __restrict__ gamma,
                                                const float* __restrict__ beta,
                                                float* __restrict__ C, int M) {
    constexpr int STR = 136;             // 136 % 32 == 8 -> conflict-free frag loads
    constexpr int NCHUNK = KD / 32;
    constexpr int WM = MT / 32;          // warps along M: 4 or 2
    constexpr int WN = 8 / WM;           // warps along N: 2 or 4
    constexpr int CW = 128 / WN;         // cols per warp: 64 or 32
    constexpr int JMAX = CW / 8;         // 8 or 4
    constexpr int TPR = 256 / MT;        // threads per A-row: 2 or 4
    constexpr int KPT = 32 / TPR;        // k floats per thread: 16 or 8
    constexpr int NF4 = KPT / 4;         // float4s per thread: 4 or 2

    extern __shared__ uint32_t smem_u[];
    uint32_t* As = smem_u;                    // 2 * 32 * STR
    uint32_t* Bs = smem_u + 2 * 32 * STR;     // 2 * 32 * STR
    float* sc1 = (float*)(smem_u + 4 * 32 * STR);   // [KD] when NORM
    float* sh1 = sc1 + (NORM ? KD : 0);

    const int tid  = threadIdx.x;
    const int lane = tid & 31;
    const int wid  = tid >> 5;
    const int g = lane >> 2, t = lane & 3;
    const int wm = wid % WM, wn = wid / WM;
    const int bm = blockIdx.x * MT;
    const int bn = blockIdx.y * 128;

    if (NORM) {
        const float invM = 1.0f / (float)N_NODES;
        for (int i = tid; i < KD; i += 256) {
            float m = g_sum1[i] * invM;
            float var = g_sq1[i] * invM - m * m;
            float sc = gamma[i] * rsqrtf(var + EPS_BN);
            sc1[i] = sc;
            sh1[i] = beta[i] - m * sc;
        }
        __syncthreads();
    }

    const int la_row = tid / TPR;
    const int la_k   = (tid % TPR) * KPT;
    const int gr_a   = bm + la_row;

    float acc[2][JMAX][4];
    #pragma unroll
    for (int f = 0; f < 2; f++)
        #pragma unroll
        for (int j = 0; j < JMAX; j++)
            #pragma unroll
            for (int q = 0; q < 4; q++) acc[f][j][q] = 0.f;

    auto loadA = [&](int c, float4* pre) {
        int k0 = c * 32 + la_k;
        #pragma unroll
        for (int i = 0; i < NF4; i++) {
            float4 v = make_float4(0.f, 0.f, 0.f, 0.f);
            if (gr_a < M) v = *(const float4*)(A + (size_t)gr_a * KD + k0 + i * 4);
            if (NORM) {
                int kk = k0 + i * 4;
                v.x = fmaf(v.x, sc1[kk + 0], sh1[kk + 0]);
                v.y = fmaf(v.y, sc1[kk + 1], sh1[kk + 1]);
                v.z = fmaf(v.z, sc1[kk + 2], sh1[kk + 2]);
                v.w = fmaf(v.w, sc1[kk + 3], sh1[kk + 3]);
            }
            pre[i] = v;
        }
    };
    auto storeA = [&](int buf, const float4* pre) {
        uint32_t* Ab = As + buf * (32 * STR);
        #pragma unroll
        for (int i = 0; i < NF4; i++) {
            int kl = la_k + i * 4;
            Ab[(kl + 0) * STR + la_row] = f2tf32(pre[i].x);
            Ab[(kl + 1) * STR + la_row] = f2tf32(pre[i].y);
            Ab[(kl + 2) * STR + la_row] = f2tf32(pre[i].z);
            Ab[(kl + 3) * STR + la_row] = f2tf32(pre[i].w);
        }
    };
    auto loadB = [&](int c, float4* pre) {
        #pragma unroll
        for (int q = 0; q < 4; q++) {
            int i = tid + q * 256;           // 0..1023
            int kl = i >> 5;                 // 0..31
            int n  = (i & 31) * 4;           // 0..124
            pre[q] = *(const float4*)(W + (size_t)(c * 32 + kl) * NC + bn + n);
        }
    };
    auto storeB = [&](int buf, const float4* pre) {
        uint32_t* Bb = Bs + buf * (32 * STR);
        #pragma unroll
        for (int q = 0; q < 4; q++) {
            int i = tid + q * 256;
            int kl = i >> 5;
            int n  = (i & 31) * 4;
            uint4 u;
            u.x = f2tf32(pre[q].x); u.y = f2tf32(pre[q].y);
            u.z = f2tf32(pre[q].z); u.w = f2tf32(pre[q].w);
            *(uint4*)&Bb[kl * STR + n] = u;
        }
    };
    auto compute = [&](int buf) {
        const uint32_t* Ab = As + buf * (32 * STR);
        const uint32_t* Bb = Bs + buf * (32 * STR);
        #pragma unroll
        for (int ks = 0; ks < 4; ks++) {
            int kt = ks * 8 + t;
            uint32_t a[2][4];
            #pragma unroll
            for (int f = 0; f < 2; f++) {
                int row = wm * 32 + f * 16 + g;
                a[f][0] = Ab[kt * STR + row];
                a[f][1] = Ab[kt * STR + row + 8];
                a[f][2] = Ab[(kt + 4) * STR + row];
                a[f][3] = Ab[(kt + 4) * STR + row + 8];
            }
            #pragma unroll
            for (int j = 0; j < JMAX; j++) {
                int col = wn * CW + j * 8 + g;
                uint32_t b0 = Bb[kt * STR + col];
                uint32_t b1 = Bb[(kt + 4) * STR + col];
                mma8(acc[0][j][0], acc[0][j][1], acc[0][j][2], acc[0][j][3],
                     a[0][0], a[0][1], a[0][2], a[0][3], b0, b1);
                mma8(acc[1][j][0], acc[1][j][1], acc[1][j][2], acc[1][j][3],
                     a[1][0], a[1][1], a[1][2], a[1][3], b0, b1);
            }
        }
    };

    float4 preA[NF4], preB[4];
    loadA(0, preA); loadB(0, preB);
    storeA(0, preA); storeB(0, preB);
    __syncthreads();
    int buf = 0;
    for (int c = 1; c < NCHUNK; c++) {
        loadA(c, preA); loadB(c, preB);
        compute(buf);
        storeA(buf ^ 1, preA); storeB(buf ^ 1, preB);
        __syncthreads();
        buf ^= 1;
    }
    compute(buf);

    // ---- epilogue: regs -> gmem (+bias,relu) ; fused stats ----
    #pragma unroll
    for (int f = 0; f < 2; f++) {
        int r0 = bm + wm * 32 + f * 16 + g;
        #pragma unroll
        for (int j = 0; j < JMAX; j++) {
            int gc = bn + wn * CW + j * 8 + 2 * t;
            float2 v0 = make_float2(acc[f][j][0], acc[f][j][1]);
            float2 v1 = make_float2(acc[f][j][2], acc[f][j][3]);
            if (RELU) {
                float b0v = bias[gc], b1v = bias[gc + 1];
                v0.x = fmaxf(v0.x + b0v, 0.f); v0.y = fmaxf(v0.y + b1v, 0.f);
                v1.x = fmaxf(v1.x + b0v, 0.f); v1.y = fmaxf(v1.y + b1v, 0.f);
            }
            if (r0 < M)     *(float2*)(C + (size_t)r0 * NC + gc)       = v0;
            if (r0 + 8 < M) *(float2*)(C + (size_t)(r0 + 8) * NC + gc) = v1;
            if (STATS) {
                bool m0 = r0 < M, m1 = (r0 + 8) < M;
                float s0 = (m0 ? v0.x : 0.f) + (m1 ? v1.x : 0.f);
                float s1 = (m0 ? v0.y : 0.f) + (m1 ? v1.y : 0.f);
                float q0 = (m0 ? v0.x * v0.x : 0.f) + (m1 ? v1.x * v1.x : 0.f);
                float q1 = (m0 ? v0.y * v0.y : 0.f) + (m1 ? v1.y * v1.y : 0.f);
                #pragma unroll
                for (int off = 4; off < 32; off <<= 1) {
                    s0 += __shfl_xor_sync(0xffffffffu, s0, off);
                    s1 += __shfl_xor_sync(0xffffffffu, s1, off);
                    q0 += __shfl_xor_sync(0xffffffffu, q0, off);
                    q1 += __shfl_xor_sync(0xffffffffu, q1, off);
                }
                if (lane < 4) {
                    int cc = bn + wn * CW + j * 8 + 2 * lane;
                    atomicAdd(&g_sum1[cc], s0);
                    atomicAdd(&g_sum1[cc + 1], s1);
                    atomicAdd(&g_sq1[cc], q0);
                    atomicAdd(&g_sq1[cc + 1], q1);
                }
            }
        }
    }
}

// ---------------- final: apply BN2 affine to per-graph max/min ----------------
__global__ void k_final(const float* __restrict__ gamma, const float* __restrict__ beta,
                        float* __restrict__ out) {
    __shared__ float sc[EMB_DIM], shf[EMB_DIM];
    int tid = threadIdx.x;
    if (tid < EMB_DIM) {
        const float invM = 1.0f / (float)N_NODES;
        float m = g_sum2[tid] * invM;
        float var = g_sq2[tid] * invM - m * m;
        float s = gamma[tid] * rsqrtf(var + EPS_BN);
        sc[tid] = s;
        shf[tid] = beta[tid] - m * s;
    }
    __syncthreads();
    int idx = blockIdx.x * blockDim.x + tid;
    if (idx >= N_GRAPHS * EMB_DIM) return;
    int c = idx & 127;
    float s = sc[c];
    float v = (s >= 0.f) ? g_vmax[idx] : g_vmin[idx];
    out[idx] = fmaf(s, v, shf[c]);
}

// ---------------- launch ----------------
extern "C" void kernel_launch(void* const* d_in, const int* in_sizes, int n_in,
                              void* d_out, int out_size) {
    const float* x      = (const float*)d_in[0];
    const int*   ei     = (const int*)d_in[1];
    const int*   batch  = (const int*)d_in[2];
    const float* W1     = (const float*)d_in[3];
    const float* b1     = (const float*)d_in[4];
    const float* gamma1 = (const float*)d_in[5];
    const float* beta1  = (const float*)d_in[6];
    const float* W2     = (const float*)d_in[7];
    const float* b2     = (const float*)d_in[8];
    const float* gamma2 = (const float*)d_in[9];
    const float* beta2  = (const float*)d_in[10];
    float* out = (float*)d_out;

    const int* src = ei;
    const int* dst = ei + N_EDGES;

    float *p_agg1, *p_h1r, *p_h2;
    cudaGetSymbolAddress((void**)&p_agg1, g_agg1);
    cudaGetSymbolAddress((void**)&p_h1r,  g_h1r);
    cudaGetSymbolAddress((void**)&p_h2,   g_h2);

    const int SMEM1 = (4 * 32 * 136) * 4;                    // 69632
    const int SMEM2 = (4 * 32 * 136 + 2 * HID_DIM) * 4;      // 71680
    cudaFuncSetAttribute(k_mma<128, IN_DIM, HID_DIM, true, false, true>,
                         cudaFuncAttributeMaxDynamicSharedMemorySize, SMEM1);
    cudaFuncSetAttribute(k_mma<64, HID_DIM, EMB_DIM, false, true, false>,
                         cudaFuncAttributeMaxDynamicSharedMemorySize, SMEM2);

    // init + degrees + CSR build (scan fused into one lookback kernel)
    k_zero<<<(N_GRAPHS * EMB_DIM + 255) / 256, 256>>>();
    k_deg<<<(N_EDGES + 255) / 256, 256>>>(dst);
    k_scan<<<SCAN_NBLK, SCAN_TPB>>>();
    k_fill<<<(N_EDGES + 255) / 256, 256>>>(src, dst);

    // layer 1: aggregate (linearity), then tf32 GEMM (+bias+relu+stats1)
    k_gather<false><<<(N_NODES * 32 + 255) / 256, 256>>>(x, p_agg1, nullptr, nullptr);
    {
        dim3 grid((N_NODES + 127) / 128, HID_DIM / 128);     // 391 x 2
        k_mma<128, IN_DIM, HID_DIM, true, false, true><<<grid, 256, SMEM1>>>(
            p_agg1, W1, b1, nullptr, nullptr, p_h1r, N_NODES);
    }

    // layer 2: GEMM with MT=64 for wave balance (782 CTAs), bn1 in-kernel
    {
        dim3 grid((N_NODES + 63) / 64, EMB_DIM / 128);       // 782 x 1
        k_mma<64, HID_DIM, EMB_DIM, false, true, false><<<grid, 256, SMEM2>>>(
            p_h1r, W2, nullptr, gamma1, beta1, p_h2, N_NODES);
    }
    k_gather<true><<<(N_NODES * 32 + 255) / 256, 256>>>(p_h2, nullptr, b2, batch);

    // output: BN2 affine on per-graph extrema
    k_final<<<(N_GRAPHS * EMB_DIM + 255) / 256, 256>>>(gamma2, beta2, out);
}